// round 1
// baseline (speedup 1.0000x reference)
#include <cuda_runtime.h>
#include <cuda_bf16.h>
#include <stdint.h>

// Problem constants
#define BATCH   128
#define TSTEPS  512
#define DIN     512
#define DOUT    512
#define MROWS   (BATCH * TSTEPS)        // 65536
#define BETA    0.95f
#define THRESH  1.0f

// Scratch: currents [B, T, DOUT] = 128 MiB, static device global (bss, no runtime alloc)
__device__ float g_currents[(size_t)MROWS * DOUT];
__device__ unsigned long long g_spike_count;

// ---------------------------------------------------------------------------
// Kernel 0: zero the spike counter (graph replays must be deterministic)
// ---------------------------------------------------------------------------
__global__ void zero_count_kernel() {
    g_spike_count = 0ull;
}

// ---------------------------------------------------------------------------
// Kernel 1: fp32 GEMM  C[m,n] = sum_k A[m,k] * W[n,k] + bias[n]
//   A = x_seq flattened [M=65536, K=512] row-major
//   W = [DOUT=512, K=512] row-major  (both K-major: no transpose needed)
// 128x128 block tile, BK=16, 256 threads, 8x8 register tile per thread.
// ---------------------------------------------------------------------------
#define BM 128
#define BN 128
#define BK 16

__global__ __launch_bounds__(256, 2)
void gemm_kernel(const float* __restrict__ A,
                 const float* __restrict__ Wm,
                 const float* __restrict__ bias,
                 float* __restrict__ C)
{
    __shared__ float As[BK][BM];
    __shared__ float Bs[BK][BN];

    const int tid = threadIdx.x;
    const int tx = tid & 15;        // 0..15 -> N direction
    const int ty = tid >> 4;        // 0..15 -> M direction
    const int rowBase = blockIdx.y * BM;
    const int colBase = blockIdx.x * BN;
    const int K = DIN;

    float acc[8][8];
#pragma unroll
    for (int i = 0; i < 8; i++)
#pragma unroll
        for (int j = 0; j < 8; j++) acc[i][j] = 0.0f;

    for (int k0 = 0; k0 < K; k0 += BK) {
        // Load A tile: 128 rows x 16 cols = 512 float4, 2 per thread
#pragma unroll
        for (int l = 0; l < 2; l++) {
            int idx = tid + l * 256;     // 0..511
            int r  = idx >> 2;           // 0..127
            int cv = idx & 3;            // which float4 in the 16-wide row
            float4 v = *(const float4*)(A + (size_t)(rowBase + r) * K + k0 + cv * 4);
            As[cv * 4 + 0][r] = v.x;
            As[cv * 4 + 1][r] = v.y;
            As[cv * 4 + 2][r] = v.z;
            As[cv * 4 + 3][r] = v.w;
        }
        // Load W tile: same shape
#pragma unroll
        for (int l = 0; l < 2; l++) {
            int idx = tid + l * 256;
            int r  = idx >> 2;
            int cv = idx & 3;
            float4 v = *(const float4*)(Wm + (size_t)(colBase + r) * K + k0 + cv * 4);
            Bs[cv * 4 + 0][r] = v.x;
            Bs[cv * 4 + 1][r] = v.y;
            Bs[cv * 4 + 2][r] = v.z;
            Bs[cv * 4 + 3][r] = v.w;
        }
        __syncthreads();

#pragma unroll
        for (int k = 0; k < BK; k++) {
            float a[8], bb[8];
#pragma unroll
            for (int i = 0; i < 8; i++) a[i] = As[k][ty * 8 + i];
#pragma unroll
            for (int j = 0; j < 8; j++) bb[j] = Bs[k][tx * 8 + j];
#pragma unroll
            for (int i = 0; i < 8; i++)
#pragma unroll
                for (int j = 0; j < 8; j++)
                    acc[i][j] = fmaf(a[i], bb[j], acc[i][j]);
        }
        __syncthreads();
    }

    // Epilogue: add bias, store
#pragma unroll
    for (int i = 0; i < 8; i++) {
        int r = rowBase + ty * 8 + i;
#pragma unroll
        for (int j = 0; j < 8; j += 4) {
            int c = colBase + tx * 8 + j;
            float4 o;
            o.x = acc[i][j + 0] + bias[c + 0];
            o.y = acc[i][j + 1] + bias[c + 1];
            o.z = acc[i][j + 2] + bias[c + 2];
            o.w = acc[i][j + 3] + bias[c + 3];
            *(float4*)(C + (size_t)r * DOUT + c) = o;
        }
    }
}

// ---------------------------------------------------------------------------
// Kernel 2: LIF scan over T. One thread per (b, d): sequential recurrence,
// coalesced loads/stores across d. Counts spikes for the sum output.
// ---------------------------------------------------------------------------
__global__ __launch_bounds__(256)
void lif_scan_kernel(const float* __restrict__ cur,
                     float* __restrict__ spikes)
{
    const int idx = blockIdx.x * blockDim.x + threadIdx.x;   // b*DOUT + d
    const int b = idx >> 9;
    const int d = idx & (DOUT - 1);

    const float* cp = cur    + (size_t)b * TSTEPS * DOUT + d;
    float*       sp = spikes + (size_t)b * TSTEPS * DOUT + d;

    float mem = 0.0f;
    int cnt = 0;
#pragma unroll 8
    for (int t = 0; t < TSTEPS; t++) {
        float c = cp[(size_t)t * DOUT];
        mem = fmaf(BETA, mem, c);            // beta*mem + cur
        float spk = (mem > THRESH) ? 1.0f : 0.0f;
        mem -= spk * THRESH;                 // reset-by-subtraction
        sp[(size_t)t * DOUT] = spk;
        cnt += (spk > 0.0f) ? 1 : 0;
    }

    // warp reduction of spike counts
#pragma unroll
    for (int off = 16; off > 0; off >>= 1)
        cnt += __shfl_down_sync(0xffffffffu, cnt, off);
    if ((threadIdx.x & 31) == 0)
        atomicAdd(&g_spike_count, (unsigned long long)cnt);
}

// ---------------------------------------------------------------------------
// Kernel 3: write scalar sum as float into the last output element
// ---------------------------------------------------------------------------
__global__ void write_sum_kernel(float* __restrict__ out, int sum_idx) {
    out[sum_idx] = (float)g_spike_count;
}

// ---------------------------------------------------------------------------
extern "C" void kernel_launch(void* const* d_in, const int* in_sizes, int n_in,
                              void* d_out, int out_size)
{
    const float* x    = (const float*)d_in[0];   // [B, T, DIN]
    const float* Wm   = (const float*)d_in[1];   // [DOUT, DIN]
    const float* bias = (const float*)d_in[2];   // [DOUT]
    float* out = (float*)d_out;                  // [B*T*DOUT] spikes + [1] sum

    float* currents;
    cudaGetSymbolAddress((void**)&currents, g_currents);

    zero_count_kernel<<<1, 1>>>();

    dim3 gemm_grid(DOUT / BN, MROWS / BM);       // (4, 512)
    gemm_kernel<<<gemm_grid, 256>>>(x, Wm, bias, currents);

    const int n_lanes = BATCH * DOUT;            // 65536
    lif_scan_kernel<<<n_lanes / 256, 256>>>(currents, out);

    write_sum_kernel<<<1, 1>>>(out, out_size - 1);
}

// round 2
// speedup vs baseline: 1.1785x; 1.1785x over previous
#include <cuda_runtime.h>
#include <cuda_bf16.h>
#include <stdint.h>

// Problem constants
#define BATCH   128
#define TSTEPS  512
#define DIN     512
#define DOUT    512
#define MROWS   (BATCH * TSTEPS)        // 65536
#define BETA    0.95f
#define THRESH  1.0f

// Scratch: currents [B, T, DOUT] = 128 MiB, static device global
__device__ float g_currents[(size_t)MROWS * DOUT];
__device__ unsigned long long g_spike_count;

// ---------------------------------------------------------------------------
// packed f32x2 helpers (Blackwell sm_100+)
// ---------------------------------------------------------------------------
__device__ __forceinline__ unsigned long long pack2(float x, float y) {
    unsigned long long r;
    asm("mov.b64 %0, {%1, %2};" : "=l"(r) : "f"(x), "f"(y));
    return r;
}
__device__ __forceinline__ void unpack2(unsigned long long v, float& x, float& y) {
    asm("mov.b64 {%0, %1}, %2;" : "=f"(x), "=f"(y) : "l"(v));
}
__device__ __forceinline__ void ffma2(unsigned long long& d,
                                      unsigned long long a,
                                      unsigned long long b) {
    // d = a * b + d, two independent IEEE fp32 fmas per instruction
    asm("fma.rn.f32x2 %0, %1, %2, %0;" : "+l"(d) : "l"(a), "l"(b));
}

// ---------------------------------------------------------------------------
__global__ void zero_count_kernel() { g_spike_count = 0ull; }

// ---------------------------------------------------------------------------
// fp32 GEMM via packed FFMA2.
//   C[m,n] = sum_k A[m,k] * W[n,k] + bias[n]
// Tile: BM=128 x BN=256, BK=16, 256 threads, 8x16 register tile (64 FFMA2/k).
// Smem: transposed tiles with XOR swizzle (phys col = m ^ ((k>>2)<<3)):
//   conflict-free for both the transposing STS.32 stores and the LDS.128
//   fragment loads. Double-buffered, 1 __syncthreads per k0 iteration.
// ---------------------------------------------------------------------------
#define BM 128
#define BN 256
#define BK 16
#define NK0 (DIN / BK)   // 32

__global__ __launch_bounds__(256, 1)
void gemm_kernel(const float* __restrict__ A,
                 const float* __restrict__ Wm,
                 const float* __restrict__ bias,
                 float* __restrict__ C)
{
    __shared__ float As[2][BK * BM];   // 16 KB
    __shared__ float Bs[2][BK * BN];   // 32 KB  (total 48 KB static)

    const int tid = threadIdx.x;
    const int tx = tid & 15;           // N direction: cols tx*4 + g*64
    const int ty = tid >> 4;           // M direction: rows ty*4 + {0,64}
    const int rowBase = blockIdx.y * BM;
    const int colBase = blockIdx.x * BN;

    unsigned long long acc[8][8];      // [row i][col-pair p], 128 regs
#pragma unroll
    for (int i = 0; i < 8; i++)
#pragma unroll
        for (int p = 0; p < 8; p++) acc[i][p] = 0ull;

    float4 ra[2], rb[4];               // global->reg staging

    // ---- stage k0 = 0 ----
#pragma unroll
    for (int l = 0; l < 2; l++) {
        int idx = tid + l * 256, r = idx >> 2, cv = idx & 3;
        ra[l] = *(const float4*)(A + (size_t)(rowBase + r) * DIN + cv * 4);
    }
#pragma unroll
    for (int l = 0; l < 4; l++) {
        int idx = tid + l * 256, r = idx >> 2, cv = idx & 3;
        rb[l] = *(const float4*)(Wm + (size_t)(colBase + r) * DIN + cv * 4);
    }
#pragma unroll
    for (int l = 0; l < 2; l++) {
        int idx = tid + l * 256, r = idx >> 2, cv = idx & 3;
        int xr = r ^ (cv << 3);
        As[0][(cv * 4 + 0) * BM + xr] = ra[l].x;
        As[0][(cv * 4 + 1) * BM + xr] = ra[l].y;
        As[0][(cv * 4 + 2) * BM + xr] = ra[l].z;
        As[0][(cv * 4 + 3) * BM + xr] = ra[l].w;
    }
#pragma unroll
    for (int l = 0; l < 4; l++) {
        int idx = tid + l * 256, r = idx >> 2, cv = idx & 3;
        int xr = r ^ (cv << 3);
        Bs[0][(cv * 4 + 0) * BN + xr] = rb[l].x;
        Bs[0][(cv * 4 + 1) * BN + xr] = rb[l].y;
        Bs[0][(cv * 4 + 2) * BN + xr] = rb[l].z;
        Bs[0][(cv * 4 + 3) * BN + xr] = rb[l].w;
    }
    __syncthreads();

    for (int j = 0; j < NK0; j++) {
        const int buf = j & 1;

        // prefetch next tile into registers (overlaps with compute)
        if (j < NK0 - 1) {
            int k0n = (j + 1) * BK;
#pragma unroll
            for (int l = 0; l < 2; l++) {
                int idx = tid + l * 256, r = idx >> 2, cv = idx & 3;
                ra[l] = *(const float4*)(A + (size_t)(rowBase + r) * DIN + k0n + cv * 4);
            }
#pragma unroll
            for (int l = 0; l < 4; l++) {
                int idx = tid + l * 256, r = idx >> 2, cv = idx & 3;
                rb[l] = *(const float4*)(Wm + (size_t)(colBase + r) * DIN + k0n + cv * 4);
            }
        }

        // ---- compute on smem[buf] ----
#pragma unroll
        for (int k = 0; k < BK; k++) {
            const int sw = (k >> 2) << 3;
            float4 a0 = *(const float4*)&As[buf][k * BM + ((ty * 4) ^ sw)];
            float4 a1 = *(const float4*)&As[buf][k * BM + ((64 + ty * 4) ^ sw)];
            unsigned long long bp[8];
#pragma unroll
            for (int g = 0; g < 4; g++) {
                ulonglong2 bb = *(const ulonglong2*)
                    &Bs[buf][k * BN + ((g * 64 + tx * 4) ^ sw)];
                bp[g * 2 + 0] = bb.x;
                bp[g * 2 + 1] = bb.y;
            }
            unsigned long long ad[8];
            ad[0] = pack2(a0.x, a0.x);  ad[1] = pack2(a0.y, a0.y);
            ad[2] = pack2(a0.z, a0.z);  ad[3] = pack2(a0.w, a0.w);
            ad[4] = pack2(a1.x, a1.x);  ad[5] = pack2(a1.y, a1.y);
            ad[6] = pack2(a1.z, a1.z);  ad[7] = pack2(a1.w, a1.w);
#pragma unroll
            for (int i = 0; i < 8; i++)
#pragma unroll
                for (int p = 0; p < 8; p++)
                    ffma2(acc[i][p], ad[i], bp[p]);
        }

        // ---- store staged tile into the other buffer ----
        if (j < NK0 - 1) {
            const int nb = buf ^ 1;
#pragma unroll
            for (int l = 0; l < 2; l++) {
                int idx = tid + l * 256, r = idx >> 2, cv = idx & 3;
                int xr = r ^ (cv << 3);
                As[nb][(cv * 4 + 0) * BM + xr] = ra[l].x;
                As[nb][(cv * 4 + 1) * BM + xr] = ra[l].y;
                As[nb][(cv * 4 + 2) * BM + xr] = ra[l].z;
                As[nb][(cv * 4 + 3) * BM + xr] = ra[l].w;
            }
#pragma unroll
            for (int l = 0; l < 4; l++) {
                int idx = tid + l * 256, r = idx >> 2, cv = idx & 3;
                int xr = r ^ (cv << 3);
                Bs[nb][(cv * 4 + 0) * BN + xr] = rb[l].x;
                Bs[nb][(cv * 4 + 1) * BN + xr] = rb[l].y;
                Bs[nb][(cv * 4 + 2) * BN + xr] = rb[l].z;
                Bs[nb][(cv * 4 + 3) * BN + xr] = rb[l].w;
            }
            __syncthreads();
        }
    }

    // ---- epilogue: bias + store ----
#pragma unroll
    for (int i = 0; i < 8; i++) {
        int r = rowBase + ((i < 4) ? (ty * 4 + i) : (64 + ty * 4 + (i - 4)));
#pragma unroll
        for (int g = 0; g < 4; g++) {
            int c = colBase + g * 64 + tx * 4;
            float4 o;
            unpack2(acc[i][g * 2 + 0], o.x, o.y);
            unpack2(acc[i][g * 2 + 1], o.z, o.w);
            o.x += bias[c + 0];
            o.y += bias[c + 1];
            o.z += bias[c + 2];
            o.w += bias[c + 3];
            *(float4*)(C + (size_t)r * DOUT + c) = o;
        }
    }
}

// ---------------------------------------------------------------------------
// LIF scan: one thread per (b, d), sequential over T, coalesced across d.
// ---------------------------------------------------------------------------
__global__ __launch_bounds__(256)
void lif_scan_kernel(const float* __restrict__ cur,
                     float* __restrict__ spikes)
{
    const int idx = blockIdx.x * blockDim.x + threadIdx.x;   // b*DOUT + d
    const int b = idx >> 9;
    const int d = idx & (DOUT - 1);

    const float* cp = cur    + (size_t)b * TSTEPS * DOUT + d;
    float*       sp = spikes + (size_t)b * TSTEPS * DOUT + d;

    float mem = 0.0f;
    int cnt = 0;
#pragma unroll 8
    for (int t = 0; t < TSTEPS; t++) {
        float c = cp[(size_t)t * DOUT];
        mem = fmaf(BETA, mem, c);
        float spk = (mem > THRESH) ? 1.0f : 0.0f;
        mem -= spk * THRESH;
        sp[(size_t)t * DOUT] = spk;
        cnt += (spk > 0.0f) ? 1 : 0;
    }

#pragma unroll
    for (int off = 16; off > 0; off >>= 1)
        cnt += __shfl_down_sync(0xffffffffu, cnt, off);
    if ((threadIdx.x & 31) == 0)
        atomicAdd(&g_spike_count, (unsigned long long)cnt);
}

__global__ void write_sum_kernel(float* __restrict__ out, int sum_idx) {
    out[sum_idx] = (float)g_spike_count;
}

// ---------------------------------------------------------------------------
extern "C" void kernel_launch(void* const* d_in, const int* in_sizes, int n_in,
                              void* d_out, int out_size)
{
    const float* x    = (const float*)d_in[0];   // [B, T, DIN]
    const float* Wm   = (const float*)d_in[1];   // [DOUT, DIN]
    const float* bias = (const float*)d_in[2];   // [DOUT]
    float* out = (float*)d_out;

    float* currents;
    cudaGetSymbolAddress((void**)&currents, g_currents);

    zero_count_kernel<<<1, 1>>>();

    dim3 gemm_grid(DOUT / BN, MROWS / BM);       // (2, 512)
    gemm_kernel<<<gemm_grid, 256>>>(x, Wm, bias, currents);

    const int n_lanes = BATCH * DOUT;            // 65536
    lif_scan_kernel<<<n_lanes / 256, 256>>>(currents, out);

    write_sum_kernel<<<1, 1>>>(out, out_size - 1);
}